// round 3
// baseline (speedup 1.0000x reference)
#include <cuda_runtime.h>
#include <math.h>
#include <stdint.h>
#include <stddef.h>

#define NT    768
#define NH    12
#define DIM   384
#define PD    128
#define FEAT  2112
#define NPROJ 1152

#define SCALAR_SCALE 0.14433756729740643f
#define POINT_SCALE  0.13608276348795434f
#define PAIR_SCALE   0.57735026918962584f

// ------------- device scratch (static, no allocation) -------------
__device__ __align__(16) float g_wall [DIM * NPROJ];
__device__ __align__(16) float g_proj [NT * NPROJ];
__device__ __align__(16) float g_qs   [NH * NT * 16];
__device__ __align__(16) float g_ks   [NH * NT * 16];
__device__ __align__(16) float g_vs   [NH * NT * 16];
__device__ __align__(16) float g_qpg  [NH * NT * 12];
__device__ __align__(16) float g_kpg  [NH * NT * 12];
__device__ __align__(16) float g_vpg  [NH * NT * 24];
__device__ __align__(16) float g_bias [(size_t)NH * NT * NT];
__device__ __align__(16) float g_feats[(size_t)NT * FEAT];

// ------------- pack weights -------------
__global__ __launch_bounds__(256) void pack_w(
    const float* __restrict__ Wq,  const float* __restrict__ Wk,
    const float* __restrict__ Wv,  const float* __restrict__ Wpq,
    const float* __restrict__ Wpk, const float* __restrict__ Wpv)
{
    int e = blockIdx.x * 256 + threadIdx.x;
    if (e >= DIM * NPROJ) return;
    int r = e / NPROJ, c = e % NPROJ;
    float v;
    if      (c < 192) v = Wq [r*192 + c];
    else if (c < 384) v = Wk [r*192 + (c-192)];
    else if (c < 576) v = Wv [r*192 + (c-384)];
    else if (c < 720) v = Wpq[r*144 + (c-576)];
    else if (c < 864) v = Wpk[r*144 + (c-720)];
    else              v = Wpv[r*288 + (c-864)];
    g_wall[e] = v;
}

// ------------- tiled SGEMM (exact-divisible shapes) -------------
__global__ __launch_bounds__(256) void sgemm64(
    const float* __restrict__ A, const float* __restrict__ B,
    float* __restrict__ C, const float* __restrict__ bias,
    int M, int N, int K)
{
    __shared__ float As[16][65];
    __shared__ float Bs[16][64];
    const int tid = threadIdx.x;
    const int tx = tid % 16, ty = tid / 16;
    const int row0 = blockIdx.y * 64, col0 = blockIdx.x * 64;

    float acc[4][4];
#pragma unroll
    for (int m = 0; m < 4; m++)
#pragma unroll
        for (int n = 0; n < 4; n++) acc[m][n] = 0.f;

    for (int k0 = 0; k0 < K; k0 += 16) {
        {   // load A tile 64x16 (256 float4)
            int r = tid / 4, c4 = tid % 4;
            float4 v = *reinterpret_cast<const float4*>(&A[(size_t)(row0+r)*K + k0 + c4*4]);
            As[c4*4+0][r] = v.x; As[c4*4+1][r] = v.y;
            As[c4*4+2][r] = v.z; As[c4*4+3][r] = v.w;
        }
        {   // load B tile 16x64
            int r = tid / 16, c4 = tid % 16;
            *reinterpret_cast<float4*>(&Bs[r][c4*4]) =
                *reinterpret_cast<const float4*>(&B[(size_t)(k0+r)*N + col0 + c4*4]);
        }
        __syncthreads();
#pragma unroll
        for (int kk = 0; kk < 16; kk++) {
            float a[4], b[4];
#pragma unroll
            for (int m = 0; m < 4; m++) a[m] = As[kk][ty*4 + m];
#pragma unroll
            for (int n = 0; n < 4; n++) b[n] = Bs[kk][tx*4 + n];
#pragma unroll
            for (int m = 0; m < 4; m++)
#pragma unroll
                for (int n = 0; n < 4; n++) acc[m][n] += a[m]*b[n];
        }
        __syncthreads();
    }
#pragma unroll
    for (int m = 0; m < 4; m++) {
        int r = row0 + ty*4 + m;
#pragma unroll
        for (int n = 0; n < 4; n++) {
            int c = col0 + tx*4 + n;
            float v = acc[m][n];
            if (bias) v += bias[c];
            C[(size_t)r*N + c] = v;
        }
    }
}

// ------------- relayout + rotate points to global frame -------------
__global__ __launch_bounds__(128) void relayout(
    const float* __restrict__ rot, const float* __restrict__ trans)
{
    const int i = blockIdx.x, t = threadIdx.x;
    __shared__ float R[9], tv[3];
    if (t < 9) R[t]  = rot[i*9 + t];
    if (t < 3) tv[t] = trans[i*3 + t];
    __syncthreads();
    const float* pr = g_proj + (size_t)i * NPROJ;
    for (int e = t; e < NH*16; e += 128) {
        int h = e/16, d = e%16;
        g_qs[((size_t)h*NT+i)*16+d] = pr[      h*16+d];
        g_ks[((size_t)h*NT+i)*16+d] = pr[192 + h*16+d];
        g_vs[((size_t)h*NT+i)*16+d] = pr[384 + h*16+d];
    }
    for (int e = t; e < NH*4; e += 128) {
        int h = e/4, p = e%4;
        const float* s = pr + 576 + h*12 + p*3;
        float x=s[0], y=s[1], z=s[2];
        float* o = g_qpg + ((size_t)h*NT+i)*12 + p*3;
        o[0]=R[0]*x+R[1]*y+R[2]*z+tv[0];
        o[1]=R[3]*x+R[4]*y+R[5]*z+tv[1];
        o[2]=R[6]*x+R[7]*y+R[8]*z+tv[2];
        s = pr + 720 + h*12 + p*3; x=s[0]; y=s[1]; z=s[2];
        o = g_kpg + ((size_t)h*NT+i)*12 + p*3;
        o[0]=R[0]*x+R[1]*y+R[2]*z+tv[0];
        o[1]=R[3]*x+R[4]*y+R[5]*z+tv[1];
        o[2]=R[6]*x+R[7]*y+R[8]*z+tv[2];
    }
    for (int e = t; e < NH*8; e += 128) {
        int h = e/8, p = e%8;
        const float* s = pr + 864 + h*24 + p*3;
        float x=s[0], y=s[1], z=s[2];
        float* o = g_vpg + ((size_t)h*NT+i)*24 + p*3;
        o[0]=R[0]*x+R[1]*y+R[2]*z+tv[0];
        o[1]=R[3]*x+R[4]*y+R[5]*z+tv[1];
        o[2]=R[6]*x+R[7]*y+R[8]*z+tv[2];
    }
}

// ------------- pair bias: warp per (i,j), coalesced pairwise reads -------------
__global__ __launch_bounds__(256) void bias_k(
    const float* __restrict__ pair, const float* __restrict__ Wpb,
    const float* __restrict__ bpb)
{
    __shared__ float w[PD*NH];
    __shared__ float bb[NH];
    for (int e = threadIdx.x; e < PD*NH; e += 256) w[e] = Wpb[e];
    if (threadIdx.x < NH) bb[threadIdx.x] = bpb[threadIdx.x];
    __syncthreads();
    int warp = (blockIdx.x*256 + threadIdx.x) >> 5;
    int lane = threadIdx.x & 31;
    int nwarp = gridDim.x * 8;
    for (int pidx = warp; pidx < NT*NT; pidx += nwarp) {
        float4 v = *reinterpret_cast<const float4*>(pair + (size_t)pidx*PD + lane*4);
        float acc[NH];
        const float* w0 = &w[(lane*4)*NH];
#pragma unroll
        for (int h = 0; h < NH; h++)
            acc[h] = v.x*w0[h] + v.y*w0[NH+h] + v.z*w0[2*NH+h] + v.w*w0[3*NH+h];
#pragma unroll
        for (int h = 0; h < NH; h++) {
            float s = acc[h];
            for (int o = 16; o; o >>= 1) s += __shfl_down_sync(~0u, s, o);
            if (lane == 0)
                g_bias[(size_t)h*NT*NT + pidx] = (s + bb[h]) * PAIR_SCALE;
        }
    }
}

// ------------- fused attention: CTA per query, 12 warps = 12 heads -------------
__global__ __launch_bounds__(384) void attn_k(
    const float* __restrict__ pair, const float* __restrict__ rot,
    const float* __restrict__ trans, const float* __restrict__ pwts)
{
    const int i = blockIdx.x;
    const int t = threadIdx.x;
    const int h = t >> 5, lane = t & 31;

    __shared__ float pr_s[32][PD];      // pair tile
    __shared__ float lt[NH][32];        // logits tile
    __shared__ float pp[NH][32];        // probs tile
    __shared__ float mstate[NH], lstate[NH], fac[NH];
    __shared__ float qs_s[NH][16];
    __shared__ float qpg_s[NH][12];
    __shared__ float acc[NH][168];      // [0,16)=scalar [16,40)=ptsg [40,168)=pair
    __shared__ float R[9], tv[3];

    float* accf = &acc[0][0];
    for (int e = t; e < NH*168; e += 384) accf[e] = 0.f;
    for (int e = t; e < NH*16;  e += 384) qs_s [e/16][e%16] = g_qs [((size_t)(e/16)*NT+i)*16 + e%16];
    for (int e = t; e < NH*12;  e += 384) qpg_s[e/12][e%12] = g_qpg[((size_t)(e/12)*NT+i)*12 + e%12];
    if (t < NH) { mstate[t] = -1e30f; lstate[t] = 0.f; }
    if (t < 9) R[t]  = rot[i*9 + t];
    if (t < 3) tv[t] = trans[i*3 + t];
    __syncthreads();

    float wv = pwts[h];
    float pwh = (wv > 20.f) ? wv : log1pf(expf(wv));
    const float pscale = -0.5f * POINT_SCALE * pwh;

    for (int j0 = 0; j0 < NT; j0 += 32) {
        // stage pair tile (coalesced float4)
        for (int e = t; e < 32*(PD/4); e += 384) {
            int r = e/(PD/4), c = e%(PD/4);
            *reinterpret_cast<float4*>(&pr_s[r][c*4]) =
                *reinterpret_cast<const float4*>(pair + ((size_t)i*NT + j0 + r)*PD + c*4);
        }
        // logits: thread (h,lane) handles j=j0+lane
        {
            int j = j0 + lane;
            const float* kr = g_ks  + ((size_t)h*NT + j)*16;
            const float* kp = g_kpg + ((size_t)h*NT + j)*12;
            float s = 0.f;
#pragma unroll
            for (int d = 0; d < 16; d++) s += qs_s[h][d]*kr[d];
            s *= SCALAR_SCALE;
            float pdist = 0.f;
#pragma unroll
            for (int c = 0; c < 12; c++) { float df = qpg_s[h][c]-kp[c]; pdist += df*df; }
            s += pscale * pdist;
            s += g_bias[(size_t)h*NT*NT + (size_t)i*NT + j];
            lt[h][lane] = s;
        }
        __syncwarp();
        // online softmax: warp h owns head h
        {
            float v = lt[h][lane];
            float mx = v;
            for (int o = 16; o; o >>= 1) mx = fmaxf(mx, __shfl_xor_sync(~0u, mx, o));
            float m_old = mstate[h];
            float m_new = fmaxf(m_old, mx);
            float p = __expf(v - m_new);
            pp[h][lane] = p;
            float ps = p;
            for (int o = 16; o; o >>= 1) ps += __shfl_xor_sync(~0u, ps, o);
            if (lane == 0) {
                float f = __expf(m_old - m_new);
                fac[h]    = f;
                lstate[h] = lstate[h]*f + ps;
                mstate[h] = m_new;
            }
        }
        __syncthreads();
        // rescale + accumulate all outputs (2016 over 384 threads)
        for (int e = t; e < NH*168; e += 384) {
            int hh = e/168, o = e%168;
            float a = accf[e] * fac[hh];
            const float* pph = pp[hh];
            if (o < 16) {
                const float* vp = g_vs + ((size_t)hh*NT + j0)*16 + o;
#pragma unroll 8
                for (int j = 0; j < 32; j++) a += pph[j]*vp[j*16];
            } else if (o < 40) {
                const float* vp = g_vpg + ((size_t)hh*NT + j0)*24 + (o-16);
#pragma unroll 8
                for (int j = 0; j < 32; j++) a += pph[j]*vp[j*24];
            } else {
                int d = o - 40;
#pragma unroll 8
                for (int j = 0; j < 32; j++) a += pph[j]*pr_s[j][d];
            }
            accf[e] = a;
        }
        __syncthreads();
    }

    // finalize
    float* fo = g_feats + (size_t)i * FEAT;
    for (int e = t; e < NH*16; e += 384) {
        int hh = e/16, d = e%16;
        fo[hh*16 + d] = acc[hh][d] / lstate[hh];
    }
    for (int e = t; e < NH*8; e += 384) {
        int hh = e/8, p = e%8;
        float inv = 1.f / lstate[hh];
        float gx = acc[hh][16+p*3+0]*inv - tv[0];
        float gy = acc[hh][16+p*3+1]*inv - tv[1];
        float gz = acc[hh][16+p*3+2]*inv - tv[2];
        float lx = R[0]*gx + R[3]*gy + R[6]*gz;
        float ly = R[1]*gx + R[4]*gy + R[7]*gz;
        float lz = R[2]*gx + R[5]*gy + R[8]*gz;
        fo[192 + hh*24 + p*3 + 0] = lx;
        fo[192 + hh*24 + p*3 + 1] = ly;
        fo[192 + hh*24 + p*3 + 2] = lz;
        fo[480 + hh*8 + p] = sqrtf(lx*lx + ly*ly + lz*lz + 1e-8f);
    }
    for (int e = t; e < NH*PD; e += 384) {
        int hh = e/PD, d = e%PD;
        fo[576 + hh*PD + d] = acc[hh][40+d] / lstate[hh];
    }
}

// ------------- launch -------------
extern "C" void kernel_launch(void* const* d_in, const int* in_sizes, int n_in,
                              void* d_out, int out_size)
{
    (void)in_sizes; (void)n_in; (void)out_size;
    const float* x     = (const float*)d_in[0];
    const float* pair  = (const float*)d_in[1];
    const float* rot   = (const float*)d_in[2];
    const float* trans = (const float*)d_in[3];
    const float* Wq    = (const float*)d_in[4];
    const float* Wk    = (const float*)d_in[5];
    const float* Wv    = (const float*)d_in[6];
    const float* Wpq   = (const float*)d_in[7];
    const float* Wpk   = (const float*)d_in[8];
    const float* Wpv   = (const float*)d_in[9];
    const float* Wpb   = (const float*)d_in[10];
    const float* bpb   = (const float*)d_in[11];
    const float* pwts  = (const float*)d_in[12];
    const float* Wout  = (const float*)d_in[13];
    const float* bout  = (const float*)d_in[14];
    float* out = (float*)d_out;

    void *p_wall, *p_proj, *p_feats;
    cudaGetSymbolAddress(&p_wall,  g_wall);
    cudaGetSymbolAddress(&p_proj,  g_proj);
    cudaGetSymbolAddress(&p_feats, g_feats);

    pack_w<<<(DIM*NPROJ + 255)/256, 256>>>(Wq, Wk, Wv, Wpq, Wpk, Wpv);
    {
        dim3 g(NPROJ/64, NT/64);
        sgemm64<<<g, 256>>>(x, (const float*)p_wall, (float*)p_proj, nullptr,
                            NT, NPROJ, DIM);
    }
    relayout<<<NT, 128>>>(rot, trans);
    bias_k<<<4608, 256>>>(pair, Wpb, bpb);
    attn_k<<<NT, 384>>>(pair, rot, trans, pwts);
    {
        dim3 g(DIM/64, NT/64);
        sgemm64<<<g, 256>>>((const float*)p_feats, Wout, out, bout,
                            NT, DIM, FEAT);
    }
}